// round 8
// baseline (speedup 1.0000x reference)
#include <cuda_runtime.h>
#include <cuda_bf16.h>
#include <math.h>
#include <stdint.h>

// Problem constants
#define D      256
#define NE     8192
#define NS     8192
#define TOPK   16
#define CAND   48     // approx top-C candidate target
#define CMAX   96     // candidate buffer cap

// Device scratch (no allocations allowed in kernel_launch)
__device__ float g_q[NE * D];
__device__ float g_k[NS * D];
__device__ float g_v[NS * D];
__device__ __align__(16) __nv_bfloat16 g_qh[NE * D];
__device__ __align__(16) __nv_bfloat16 g_kh[NS * D];
__device__ __align__(16) __nv_bfloat16 g_sb[(size_t)NE * NS];  // 128 MB approx scores

__device__ __forceinline__ uint32_t smem_u32(const void* p) {
    uint32_t a;
    asm("{ .reg .u64 t; cvta.to.shared.u64 t, %1; cvt.u32.u64 %0, t; }"
        : "=r"(a) : "l"(p));
    return a;
}

#define LDSM_X4(r0, r1, r2, r3, addr) \
    asm volatile("ldmatrix.sync.aligned.m8n8.x4.shared.b16 {%0,%1,%2,%3}, [%4];" \
                 : "=r"(r0), "=r"(r1), "=r"(r2), "=r"(r3) : "r"(addr))

#define MMA_BF16(c, a0, a1, a2, a3, b0, b1) \
    asm volatile("mma.sync.aligned.m16n8k16.row.col.f32.bf16.bf16.f32 " \
                 "{%0,%1,%2,%3}, {%4,%5,%6,%7}, {%8,%9}, {%0,%1,%2,%3};" \
                 : "+f"((c)[0]), "+f"((c)[1]), "+f"((c)[2]), "+f"((c)[3]) \
                 : "r"(a0), "r"(a1), "r"(a2), "r"(a3), "r"(b0), "r"(b1))

// ===========================================================================
// Projection GEMM (FFMA), one launch per projection (full-chip per launch):
//   dsel 0: q = ego@Wq^T+bq        -> fp32 g_q + bf16 g_qh
//   dsel 1: k = (side.*rel)@Wk^T+bk-> fp32 g_k + bf16 g_kh
//   dsel 2: v = side@Wv^T+bv       -> fp32 g_v
// ===========================================================================
__global__ void __launch_bounds__(256, 2)
proj_kernel(const float* __restrict__ A, const float* __restrict__ A2,
            const float* __restrict__ W, const float* __restrict__ bias,
            int dsel)
{
    const int bm = blockIdx.y;
    const int bn = blockIdx.x;

    __shared__ float As[2][16][128];
    __shared__ float Bs[2][16][128];

    const int tid = threadIdx.x;
    const int tx = tid & 15;
    const int ty = tid >> 4;

    const float* Ab  = A  + (size_t)(bm * 128) * D;
    const float* A2b = A2 ? (A2 + (size_t)(bm * 128) * D) : nullptr;
    const float* Bb  = W  + (size_t)(bn * 128) * D;

    float acc[8][8];
#pragma unroll
    for (int i = 0; i < 8; i++)
#pragma unroll
        for (int j = 0; j < 8; j++) acc[i][j] = 0.f;

    auto load_stage = [&](int buf, int k0) {
#pragma unroll
        for (int r = 0; r < 2; r++) {
            const int f   = tid + r * 256;
            const int row = f >> 2;
            const int kc  = (f & 3) * 4;
            float4 a = *(const float4*)(Ab + (size_t)row * D + k0 + kc);
            if (A2b) {
                float4 a2 = *(const float4*)(A2b + (size_t)row * D + k0 + kc);
                a.x *= a2.x; a.y *= a2.y; a.z *= a2.z; a.w *= a2.w;
            }
            As[buf][kc + 0][row] = a.x;
            As[buf][kc + 1][row] = a.y;
            As[buf][kc + 2][row] = a.z;
            As[buf][kc + 3][row] = a.w;
            float4 b = *(const float4*)(Bb + (size_t)row * D + k0 + kc);
            Bs[buf][kc + 0][row] = b.x;
            Bs[buf][kc + 1][row] = b.y;
            Bs[buf][kc + 2][row] = b.z;
            Bs[buf][kc + 3][row] = b.w;
        }
    };

    load_stage(0, 0);
    __syncthreads();

    const int nk = D / 16;
    for (int kt = 0; kt < nk; kt++) {
        const int buf = kt & 1;
        if (kt + 1 < nk) load_stage(buf ^ 1, (kt + 1) * 16);
#pragma unroll
        for (int kk = 0; kk < 16; kk++) {
            float4 a0 = *(const float4*)&As[buf][kk][ty * 8];
            float4 a1 = *(const float4*)&As[buf][kk][ty * 8 + 4];
            float4 b0 = *(const float4*)&Bs[buf][kk][tx * 8];
            float4 b1 = *(const float4*)&Bs[buf][kk][tx * 8 + 4];
            float av[8] = {a0.x, a0.y, a0.z, a0.w, a1.x, a1.y, a1.z, a1.w};
            float bvv[8] = {b0.x, b0.y, b0.z, b0.w, b1.x, b1.y, b1.z, b1.w};
#pragma unroll
            for (int i = 0; i < 8; i++)
#pragma unroll
                for (int j = 0; j < 8; j++)
                    acc[i][j] = fmaf(av[i], bvv[j], acc[i][j]);
        }
        __syncthreads();
    }

    const int col0 = bn * 128 + tx * 8;
    float bia[8];
#pragma unroll
    for (int j = 0; j < 8; j++) bia[j] = bias[col0 + j];

    float* Gf = (dsel == 0) ? g_q : (dsel == 1) ? g_k : g_v;
    __nv_bfloat16* Gh = (dsel == 0) ? g_qh : g_kh;

#pragma unroll
    for (int i = 0; i < 8; i++) {
        const int row = bm * 128 + ty * 8 + i;
        float v[8];
#pragma unroll
        for (int j = 0; j < 8; j++) v[j] = acc[i][j] + bia[j];
        float* crow = Gf + (size_t)row * D + col0;
        *(float4*)(crow)     = make_float4(v[0], v[1], v[2], v[3]);
        *(float4*)(crow + 4) = make_float4(v[4], v[5], v[6], v[7]);
        if (dsel != 2) {
            __nv_bfloat16* hrow = Gh + (size_t)row * D + col0;
#pragma unroll
            for (int j = 0; j < 4; j++)
                *(__nv_bfloat162*)(hrow + j * 2) =
                    __float22bfloat162_rn(make_float2(v[2 * j], v[2 * j + 1]));
        }
    }
}

// ===========================================================================
// Approx scores GEMM (bf16 HMMA mma.sync) — unchanged from R6/R7 passing.
// ===========================================================================
__global__ void __launch_bounds__(256, 2)
approx_kernel()
{
    __shared__ __align__(16) char sm[40960];  // A0,B0,A1,B1 @ 10240 each
    const int tid  = threadIdx.x;
    const int lane = tid & 31;
    const int wid  = tid >> 5;
    const int wm   = wid >> 1;
    const int wn   = wid & 1;
    const int bm   = blockIdx.y;
    const int bn   = blockIdx.x;

    const uint32_t sb0 = smem_u32(sm);
    const uint32_t uA[2] = {sb0,         sb0 + 20480};
    const uint32_t uB[2] = {sb0 + 10240, sb0 + 30720};

    float acc[2][8][4];
#pragma unroll
    for (int mt = 0; mt < 2; mt++)
#pragma unroll
        for (int nt = 0; nt < 8; nt++)
#pragma unroll
            for (int r = 0; r < 4; r++) acc[mt][nt][r] = 0.f;

    auto load_chunk = [&](int c, int b) {
        const char* srcA = (const char*)g_qh + (size_t)(bm * 128) * 512 + c * 64;
        const char* srcB = (const char*)g_kh + (size_t)(bn * 128) * 512 + c * 64;
        char* dA = sm + (b ? 20480 : 0);
        char* dB = sm + (b ? 30720 : 10240);
#pragma unroll
        for (int t = 0; t < 4; t++) {
            const int i   = tid + t * 256;
            const int til = i >> 9;
            const int idx = i & 511;
            const int r   = idx >> 2;
            const int j   = idx & 3;
            const char* s = (til ? srcB : srcA) + (size_t)r * 512 + j * 16;
            char* d = (til ? dB : dA) + r * 80 + j * 16;
            *(uint4*)d = *(const uint4*)s;
        }
    };

    const int g  = lane >> 3;
    const int lr = lane & 7;

    load_chunk(0, 0);
    __syncthreads();

    for (int c = 0; c < 8; c++) {
        const int b = c & 1;
        if (c + 1 < 8) load_chunk(c + 1, b ^ 1);
#pragma unroll
        for (int ks = 0; ks < 2; ks++) {
            const int kb = ks * 32;
            uint32_t af[2][4], bf[8][2];
#pragma unroll
            for (int mt = 0; mt < 2; mt++) {
                const uint32_t addr = uA[b] +
                    (wm * 32 + mt * 16 + (g & 1) * 8 + lr) * 80 +
                    kb + (g >> 1) * 16;
                LDSM_X4(af[mt][0], af[mt][1], af[mt][2], af[mt][3], addr);
            }
#pragma unroll
            for (int np = 0; np < 4; np++) {
                const uint32_t addr = uB[b] +
                    (wn * 64 + np * 16 + (g >> 1) * 8 + lr) * 80 +
                    kb + (g & 1) * 16;
                uint32_t r0, r1, r2, r3;
                LDSM_X4(r0, r1, r2, r3, addr);
                bf[np * 2 + 0][0] = r0; bf[np * 2 + 0][1] = r1;
                bf[np * 2 + 1][0] = r2; bf[np * 2 + 1][1] = r3;
            }
#pragma unroll
            for (int mt = 0; mt < 2; mt++)
#pragma unroll
                for (int nt = 0; nt < 8; nt++)
                    MMA_BF16(acc[mt][nt], af[mt][0], af[mt][1], af[mt][2],
                             af[mt][3], bf[nt][0], bf[nt][1]);
        }
        __syncthreads();
    }

    const int gm0 = bm * 128 + wm * 32;
    const int gn0 = bn * 128 + wn * 64;
#pragma unroll
    for (int mt = 0; mt < 2; mt++)
#pragma unroll
        for (int nt = 0; nt < 8; nt++) {
            const int r0 = gm0 + mt * 16 + (lane >> 2);
            const int c0 = gn0 + nt * 8 + (lane & 3) * 2;
            float* a = acc[mt][nt];
            *(__nv_bfloat162*)&g_sb[(size_t)r0 * NS + c0] =
                __float22bfloat162_rn(make_float2(a[0], a[1]));
            *(__nv_bfloat162*)&g_sb[(size_t)(r0 + 8) * NS + c0] =
                __float22bfloat162_rn(make_float2(a[2], a[3]));
        }
}

// ===========================================================================
// Top-K: register-resident keys, match_any-aggregated per-warp histograms,
// parallel suffix scans; approx top-48 -> exact fp32 rescore -> exact top-16.
// One block (256 threads) per ego row.
// ===========================================================================
__device__ __forceinline__ unsigned k16(unsigned h) {
    return ((h & 0x8000u) ? ~h : (h | 0x8000u)) & 0xFFFFu;
}

__global__ void __launch_bounds__(256)
topk_kernel(float* __restrict__ out)
{
    const int row  = blockIdx.x;
    const int tid  = threadIdx.x;
    const int lane = tid & 31;
    const int wid  = tid >> 5;

    __shared__ int   whist[8][256];   // 8 KB per-warp histograms
    __shared__ int   suf[256];
    __shared__ float qs[D];
    __shared__ int   cidx[CMAX];
    __shared__ float rs[CMAX];
    __shared__ float wsc[TOPK];
    __shared__ int   wix[TOPK];
    __shared__ int   sh_b1, sh_above, sh_T, nc;

    // 1) load 32 bf16 scores per thread -> monotonic u16 keys in registers
    unsigned short lk[32];
    const uint4* sp = (const uint4*)(g_sb + (size_t)row * NS);
#pragma unroll
    for (int i = 0; i < 4; i++) {
        uint4 u = sp[tid + i * 256];
        unsigned w[4] = {u.x, u.y, u.z, u.w};
#pragma unroll
        for (int j = 0; j < 4; j++) {
            lk[i * 8 + j * 2 + 0] = (unsigned short)k16(w[j] & 0xFFFFu);
            lk[i * 8 + j * 2 + 1] = (unsigned short)k16(w[j] >> 16);
        }
    }
#pragma unroll
    for (int w = 0; w < 8; w++) whist[w][tid] = 0;
    qs[tid] = g_q[(size_t)row * D + tid];
    if (tid == 0) nc = 0;
    __syncthreads();

    // 2) pass 1 histogram (high byte): warp-aggregated — bf16 high bytes
    //    concentrate into few exponent buckets, so match_any collapses the
    //    conflict set to one atomic per unique bucket per step.
#pragma unroll
    for (int i = 0; i < 32; i++) {
        const unsigned b = lk[i] >> 8;
        const unsigned m = __match_any_sync(0xffffffff, b);
        if ((int)(__ffs(m) - 1) == lane)
            atomicAdd(&whist[wid][b], __popc(m));
    }
    __syncthreads();
    {
        int h = 0;
#pragma unroll
        for (int w = 0; w < 8; w++) h += whist[w][tid];
        suf[tid] = h;
    }
    __syncthreads();
    // inclusive suffix scan (Hillis-Steele)
#pragma unroll
    for (int off = 1; off < 256; off <<= 1) {
        const int v = (tid + off < 256) ? suf[tid + off] : 0;
        __syncthreads();
        suf[tid] += v;
        __syncthreads();
    }
    if (suf[tid] >= CAND && (tid == 255 || suf[tid + 1] < CAND)) {
        sh_b1 = tid;
        sh_above = (tid == 255) ? 0 : suf[tid + 1];
    }
    whist[0][tid] = 0;   // reuse hist 0 for pass 2
    __syncthreads();
    const int b1   = sh_b1;
    const int want = CAND - sh_above;

    // 3) pass 2 histogram (low byte within bucket b1) — few participants,
    //    mantissa bits spread: plain atomics fine.
#pragma unroll
    for (int i = 0; i < 32; i++) {
        const unsigned u = lk[i];
        if ((int)(u >> 8) == b1) atomicAdd(&whist[0][u & 255], 1);
    }
    __syncthreads();
    suf[tid] = whist[0][tid];
    __syncthreads();
#pragma unroll
    for (int off = 1; off < 256; off <<= 1) {
        const int v = (tid + off < 256) ? suf[tid + off] : 0;
        __syncthreads();
        suf[tid] += v;
        __syncthreads();
    }
    if (suf[tid] >= want && (tid == 255 || suf[tid + 1] < want))
        sh_T = (b1 << 8) | tid;
    __syncthreads();
    const unsigned T = (unsigned)sh_T;

    // 4) collect candidate indices (key >= T)
#pragma unroll
    for (int i = 0; i < 4; i++)
#pragma unroll
        for (int jj = 0; jj < 8; jj++) {
            if (lk[i * 8 + jj] >= T) {
                const int p = atomicAdd(&nc, 1);
                if (p < CMAX) cidx[p] = (tid + i * 256) * 8 + jj;
            }
        }
    __syncthreads();
    const int Nc = nc < CMAX ? nc : CMAX;

    // 5) exact fp32 rescore: s = dot(q_row, k_cand) / 16  (stride-32 layout:
    //    conflict-free qs reads, coalesced k reads)
    for (int c = wid; c < Nc; c += 8) {
        const float* kr = g_k + (size_t)cidx[c] * D;
        float s = 0.f;
#pragma unroll
        for (int j = 0; j < 8; j++)
            s = fmaf(qs[lane + 32 * j], kr[lane + 32 * j], s);
#pragma unroll
        for (int o = 16; o; o >>= 1)
            s += __shfl_xor_sync(0xffffffff, s, o);
        if (lane == 0) rs[c] = s * (1.f / 16.f);
    }
    __syncthreads();

    // 6) exact top-16 (warp 0; lower index wins ties)
    if (wid == 0) {
        int used = 0;
        for (int t = 0; t < TOPK; t++) {
            float bv = -INFINITY; int bi = 0x7fffffff;
#pragma unroll
            for (int j = 0; j < 3; j++) {
                const int s = lane + 32 * j;
                if (s < Nc && !((used >> j) & 1)) {
                    const float v = rs[s];
                    const int  ix = cidx[s];
                    if (v > bv || (v == bv && ix < bi)) { bv = v; bi = ix; }
                }
            }
#pragma unroll
            for (int o = 16; o; o >>= 1) {
                const float ov = __shfl_xor_sync(0xffffffff, bv, o);
                const int   oi = __shfl_xor_sync(0xffffffff, bi, o);
                if (ov > bv || (ov == bv && oi < bi)) { bv = ov; bi = oi; }
            }
#pragma unroll
            for (int j = 0; j < 3; j++) {
                const int s = lane + 32 * j;
                if (s < Nc && cidx[s] == bi) used |= 1 << j;
            }
            if (lane == 0) { wsc[t] = bv; wix[t] = bi; }
        }
    }
    __syncthreads();

    // 7) softmax + v aggregation (thread owns one output dim)
    float m = wsc[0];
#pragma unroll
    for (int i = 1; i < TOPK; i++) m = fmaxf(m, wsc[i]);
    float e[TOPK]; float sum = 0.f;
#pragma unroll
    for (int i = 0; i < TOPK; i++) { e[i] = expf(wsc[i] - m); sum += e[i]; }
    const float inv = 1.f / sum;

    float accv = 0.f;
#pragma unroll
    for (int i = 0; i < TOPK; i++)
        accv = fmaf(e[i] * inv, g_v[(size_t)wix[i] * D + tid], accv);

    out[(size_t)row * D + tid] = accv;
}

// ---------------------------------------------------------------------------
extern "C" void kernel_launch(void* const* d_in, const int* in_sizes, int n_in,
                              void* d_out, int out_size)
{
    const float* ego  = (const float*)d_in[0];
    const float* side = (const float*)d_in[1];
    const float* rel  = (const float*)d_in[2];
    const float* Wq   = (const float*)d_in[3];
    const float* bq   = (const float*)d_in[4];
    const float* Wk   = (const float*)d_in[5];
    const float* bk   = (const float*)d_in[6];
    const float* Wv   = (const float*)d_in[7];
    const float* bv   = (const float*)d_in[8];
    float* out = (float*)d_out;

    dim3 blk(256);
    proj_kernel<<<dim3(2, 64), blk>>>(ego,  nullptr, Wq, bq, 0);
    proj_kernel<<<dim3(2, 64), blk>>>(side, rel,     Wk, bk, 1);
    proj_kernel<<<dim3(2, 64), blk>>>(side, nullptr, Wv, bv, 2);
    approx_kernel<<<dim3(64, 64), blk>>>();
    topk_kernel<<<NE, blk>>>(out);
}

// round 9
// speedup vs baseline: 1.3198x; 1.3198x over previous
#include <cuda_runtime.h>
#include <cuda_bf16.h>
#include <math.h>
#include <stdint.h>

// Problem constants
#define D      256
#define NE     8192
#define NS     8192
#define TOPK   16
#define CAND   48     // approx top-C candidate target
#define CMAX   96     // candidate buffer cap

// Device scratch (no allocations allowed in kernel_launch)
__device__ float g_q[NE * D];
__device__ float g_k[NS * D];
__device__ float g_v[NS * D];
__device__ __align__(16) __nv_bfloat16 g_qh[NE * D];
__device__ __align__(16) __nv_bfloat16 g_kh[NS * D];
__device__ __align__(16) __nv_bfloat16 g_sb[(size_t)NE * NS];  // 128 MB approx scores

__device__ __forceinline__ uint32_t smem_u32(const void* p) {
    uint32_t a;
    asm("{ .reg .u64 t; cvta.to.shared.u64 t, %1; cvt.u32.u64 %0, t; }"
        : "=r"(a) : "l"(p));
    return a;
}

#define LDSM_X4(r0, r1, r2, r3, addr) \
    asm volatile("ldmatrix.sync.aligned.m8n8.x4.shared.b16 {%0,%1,%2,%3}, [%4];" \
                 : "=r"(r0), "=r"(r1), "=r"(r2), "=r"(r3) : "r"(addr))

#define MMA_BF16(c, a0, a1, a2, a3, b0, b1) \
    asm volatile("mma.sync.aligned.m16n8k16.row.col.f32.bf16.bf16.f32 " \
                 "{%0,%1,%2,%3}, {%4,%5,%6,%7}, {%8,%9}, {%0,%1,%2,%3};" \
                 : "+f"((c)[0]), "+f"((c)[1]), "+f"((c)[2]), "+f"((c)[3]) \
                 : "r"(a0), "r"(a1), "r"(a2), "r"(a3), "r"(b0), "r"(b1))

#define CP_ASYNC16(saddr, gptr) \
    asm volatile("cp.async.cg.shared.global [%0], [%1], 16;" \
                 :: "r"(saddr), "l"(gptr) : "memory")
#define CP_COMMIT() asm volatile("cp.async.commit_group;" ::: "memory")
#define CP_WAIT0()  asm volatile("cp.async.wait_group 0;" ::: "memory")

// ===========================================================================
// Projection GEMM (FFMA), one launch per projection:
//   dsel 0: q = ego@Wq^T+bq        -> fp32 g_q + bf16 g_qh
//   dsel 1: k = (side.*rel)@Wk^T+bk-> fp32 g_k + bf16 g_kh
//   dsel 2: v = side@Wv^T+bv       -> fp32 g_v
// ===========================================================================
__global__ void __launch_bounds__(256, 2)
proj_kernel(const float* __restrict__ A, const float* __restrict__ A2,
            const float* __restrict__ W, const float* __restrict__ bias,
            int dsel)
{
    const int bm = blockIdx.y;
    const int bn = blockIdx.x;

    __shared__ float As[2][16][128];
    __shared__ float Bs[2][16][128];

    const int tid = threadIdx.x;
    const int tx = tid & 15;
    const int ty = tid >> 4;

    const float* Ab  = A  + (size_t)(bm * 128) * D;
    const float* A2b = A2 ? (A2 + (size_t)(bm * 128) * D) : nullptr;
    const float* Bb  = W  + (size_t)(bn * 128) * D;

    float acc[8][8];
#pragma unroll
    for (int i = 0; i < 8; i++)
#pragma unroll
        for (int j = 0; j < 8; j++) acc[i][j] = 0.f;

    auto load_stage = [&](int buf, int k0) {
#pragma unroll
        for (int r = 0; r < 2; r++) {
            const int f   = tid + r * 256;
            const int row = f >> 2;
            const int kc  = (f & 3) * 4;
            float4 a = *(const float4*)(Ab + (size_t)row * D + k0 + kc);
            if (A2b) {
                float4 a2 = *(const float4*)(A2b + (size_t)row * D + k0 + kc);
                a.x *= a2.x; a.y *= a2.y; a.z *= a2.z; a.w *= a2.w;
            }
            As[buf][kc + 0][row] = a.x;
            As[buf][kc + 1][row] = a.y;
            As[buf][kc + 2][row] = a.z;
            As[buf][kc + 3][row] = a.w;
            float4 b = *(const float4*)(Bb + (size_t)row * D + k0 + kc);
            Bs[buf][kc + 0][row] = b.x;
            Bs[buf][kc + 1][row] = b.y;
            Bs[buf][kc + 2][row] = b.z;
            Bs[buf][kc + 3][row] = b.w;
        }
    };

    load_stage(0, 0);
    __syncthreads();

    const int nk = D / 16;
    for (int kt = 0; kt < nk; kt++) {
        const int buf = kt & 1;
        if (kt + 1 < nk) load_stage(buf ^ 1, (kt + 1) * 16);
#pragma unroll
        for (int kk = 0; kk < 16; kk++) {
            float4 a0 = *(const float4*)&As[buf][kk][ty * 8];
            float4 a1 = *(const float4*)&As[buf][kk][ty * 8 + 4];
            float4 b0 = *(const float4*)&Bs[buf][kk][tx * 8];
            float4 b1 = *(const float4*)&Bs[buf][kk][tx * 8 + 4];
            float av[8] = {a0.x, a0.y, a0.z, a0.w, a1.x, a1.y, a1.z, a1.w};
            float bvv[8] = {b0.x, b0.y, b0.z, b0.w, b1.x, b1.y, b1.z, b1.w};
#pragma unroll
            for (int i = 0; i < 8; i++)
#pragma unroll
                for (int j = 0; j < 8; j++)
                    acc[i][j] = fmaf(av[i], bvv[j], acc[i][j]);
        }
        __syncthreads();
    }

    const int col0 = bn * 128 + tx * 8;
    float bia[8];
#pragma unroll
    for (int j = 0; j < 8; j++) bia[j] = bias[col0 + j];

    float* Gf = (dsel == 0) ? g_q : (dsel == 1) ? g_k : g_v;
    __nv_bfloat16* Gh = (dsel == 0) ? g_qh : g_kh;

#pragma unroll
    for (int i = 0; i < 8; i++) {
        const int row = bm * 128 + ty * 8 + i;
        float v[8];
#pragma unroll
        for (int j = 0; j < 8; j++) v[j] = acc[i][j] + bia[j];
        float* crow = Gf + (size_t)row * D + col0;
        *(float4*)(crow)     = make_float4(v[0], v[1], v[2], v[3]);
        *(float4*)(crow + 4) = make_float4(v[4], v[5], v[6], v[7]);
        if (dsel != 2) {
            __nv_bfloat16* hrow = Gh + (size_t)row * D + col0;
#pragma unroll
            for (int j = 0; j < 4; j++)
                *(__nv_bfloat162*)(hrow + j * 2) =
                    __float22bfloat162_rn(make_float2(v[2 * j], v[2 * j + 1]));
        }
    }
}

// ===========================================================================
// Approx scores GEMM (bf16 HMMA mma.sync). R6 structure; global->smem
// prefetch switched to cp.async so the copy never occupies the register
// pipeline (removes the long-scoreboard stall at the STS).
// ===========================================================================
__global__ void __launch_bounds__(256, 2)
approx_kernel()
{
    __shared__ __align__(16) char sm[40960];  // A0,B0,A1,B1 @ 10240 each
    const int tid  = threadIdx.x;
    const int lane = tid & 31;
    const int wid  = tid >> 5;
    const int wm   = wid >> 1;
    const int wn   = wid & 1;
    const int bm   = blockIdx.y;
    const int bn   = blockIdx.x;

    const uint32_t sb0 = smem_u32(sm);
    const uint32_t uA[2] = {sb0,         sb0 + 20480};
    const uint32_t uB[2] = {sb0 + 10240, sb0 + 30720};

    float acc[2][8][4];
#pragma unroll
    for (int mt = 0; mt < 2; mt++)
#pragma unroll
        for (int nt = 0; nt < 8; nt++)
#pragma unroll
            for (int r = 0; r < 4; r++) acc[mt][nt][r] = 0.f;

    // async chunk loader: 2 tiles of 128 rows x 32 bf16 (64B/row), stride 80B
    auto load_chunk = [&](int c, int b) {
        const char* srcA = (const char*)g_qh + (size_t)(bm * 128) * 512 + c * 64;
        const char* srcB = (const char*)g_kh + (size_t)(bn * 128) * 512 + c * 64;
#pragma unroll
        for (int t = 0; t < 4; t++) {
            const int i   = tid + t * 256;
            const int til = i >> 9;
            const int idx = i & 511;
            const int r   = idx >> 2;
            const int j   = idx & 3;
            const char* s = (til ? srcB : srcA) + (size_t)r * 512 + j * 16;
            const uint32_t d = sb0 + b * 20480 + til * 10240 + r * 80 + j * 16;
            CP_ASYNC16(d, s);
        }
        CP_COMMIT();
    };

    const int g  = lane >> 3;
    const int lr = lane & 7;

    load_chunk(0, 0);
    CP_WAIT0();
    __syncthreads();

    for (int c = 0; c < 8; c++) {
        const int b = c & 1;
        if (c + 1 < 8) load_chunk(c + 1, b ^ 1);
#pragma unroll
        for (int ks = 0; ks < 2; ks++) {
            const int kb = ks * 32;
            uint32_t af[2][4], bf[8][2];
#pragma unroll
            for (int mt = 0; mt < 2; mt++) {
                const uint32_t addr = uA[b] +
                    (wm * 32 + mt * 16 + (g & 1) * 8 + lr) * 80 +
                    kb + (g >> 1) * 16;
                LDSM_X4(af[mt][0], af[mt][1], af[mt][2], af[mt][3], addr);
            }
#pragma unroll
            for (int np = 0; np < 4; np++) {
                const uint32_t addr = uB[b] +
                    (wn * 64 + np * 16 + (g >> 1) * 8 + lr) * 80 +
                    kb + (g & 1) * 16;
                uint32_t r0, r1, r2, r3;
                LDSM_X4(r0, r1, r2, r3, addr);
                bf[np * 2 + 0][0] = r0; bf[np * 2 + 0][1] = r1;
                bf[np * 2 + 1][0] = r2; bf[np * 2 + 1][1] = r3;
            }
#pragma unroll
            for (int mt = 0; mt < 2; mt++)
#pragma unroll
                for (int nt = 0; nt < 8; nt++)
                    MMA_BF16(acc[mt][nt], af[mt][0], af[mt][1], af[mt][2],
                             af[mt][3], bf[nt][0], bf[nt][1]);
        }
        CP_WAIT0();
        __syncthreads();
    }

    const int gm0 = bm * 128 + wm * 32;
    const int gn0 = bn * 128 + wn * 64;
#pragma unroll
    for (int mt = 0; mt < 2; mt++)
#pragma unroll
        for (int nt = 0; nt < 8; nt++) {
            const int r0 = gm0 + mt * 16 + (lane >> 2);
            const int c0 = gn0 + nt * 8 + (lane & 3) * 2;
            float* a = acc[mt][nt];
            *(__nv_bfloat162*)&g_sb[(size_t)r0 * NS + c0] =
                __float22bfloat162_rn(make_float2(a[0], a[1]));
            *(__nv_bfloat162*)&g_sb[(size_t)(r0 + 8) * NS + c0] =
                __float22bfloat162_rn(make_float2(a[2], a[3]));
        }
}

// ===========================================================================
// Top-K: register-resident keys + plain per-warp histogram atomics (R7
// version — match_any variant measured +180us and was reverted).
// Approx top-48 -> exact fp32 rescore -> exact top-16 -> softmax -> aggregate.
// ===========================================================================
__device__ __forceinline__ unsigned k16(unsigned h) {
    return ((h & 0x8000u) ? ~h : (h | 0x8000u)) & 0xFFFFu;
}

__global__ void __launch_bounds__(256)
topk_kernel(float* __restrict__ out)
{
    const int row  = blockIdx.x;
    const int tid  = threadIdx.x;
    const int lane = tid & 31;
    const int wid  = tid >> 5;

    __shared__ int   whist[8][256];   // 8 KB per-warp histograms
    __shared__ int   suf[256];
    __shared__ float qs[D];
    __shared__ int   cidx[CMAX];
    __shared__ float rs[CMAX];
    __shared__ float wsc[TOPK];
    __shared__ int   wix[TOPK];
    __shared__ int   sh_b1, sh_above, sh_T, nc;

    // 1) load 32 bf16 scores per thread -> monotonic u16 keys in registers
    unsigned short lk[32];
    const uint4* sp = (const uint4*)(g_sb + (size_t)row * NS);
#pragma unroll
    for (int i = 0; i < 4; i++) {
        uint4 u = sp[tid + i * 256];
        unsigned w[4] = {u.x, u.y, u.z, u.w};
#pragma unroll
        for (int j = 0; j < 4; j++) {
            lk[i * 8 + j * 2 + 0] = (unsigned short)k16(w[j] & 0xFFFFu);
            lk[i * 8 + j * 2 + 1] = (unsigned short)k16(w[j] >> 16);
        }
    }
#pragma unroll
    for (int w = 0; w < 8; w++) whist[w][tid] = 0;
    qs[tid] = g_q[(size_t)row * D + tid];
    if (tid == 0) nc = 0;
    __syncthreads();

    // 2) pass 1 histogram (high byte) into per-warp hists
#pragma unroll
    for (int i = 0; i < 32; i++)
        atomicAdd(&whist[wid][lk[i] >> 8], 1);
    __syncthreads();
    {
        int h = 0;
#pragma unroll
        for (int w = 0; w < 8; w++) h += whist[w][tid];
        suf[tid] = h;
    }
    __syncthreads();
    // inclusive suffix scan (Hillis-Steele)
#pragma unroll
    for (int off = 1; off < 256; off <<= 1) {
        const int v = (tid + off < 256) ? suf[tid + off] : 0;
        __syncthreads();
        suf[tid] += v;
        __syncthreads();
    }
    if (suf[tid] >= CAND && (tid == 255 || suf[tid + 1] < CAND)) {
        sh_b1 = tid;
        sh_above = (tid == 255) ? 0 : suf[tid + 1];
    }
    whist[0][tid] = 0;   // reuse hist 0 for pass 2
    __syncthreads();
    const int b1   = sh_b1;
    const int want = CAND - sh_above;

    // 3) pass 2 histogram (low byte within bucket b1)
#pragma unroll
    for (int i = 0; i < 32; i++) {
        const unsigned u = lk[i];
        if ((int)(u >> 8) == b1) atomicAdd(&whist[0][u & 255], 1);
    }
    __syncthreads();
    suf[tid] = whist[0][tid];
    __syncthreads();
#pragma unroll
    for (int off = 1; off < 256; off <<= 1) {
        const int v = (tid + off < 256) ? suf[tid + off] : 0;
        __syncthreads();
        suf[tid] += v;
        __syncthreads();
    }
    if (suf[tid] >= want && (tid == 255 || suf[tid + 1] < want))
        sh_T = (b1 << 8) | tid;
    __syncthreads();
    const unsigned T = (unsigned)sh_T;

    // 4) collect candidate indices (key >= T)
#pragma unroll
    for (int i = 0; i < 4; i++)
#pragma unroll
        for (int jj = 0; jj < 8; jj++) {
            if (lk[i * 8 + jj] >= T) {
                const int p = atomicAdd(&nc, 1);
                if (p < CMAX) cidx[p] = (tid + i * 256) * 8 + jj;
            }
        }
    __syncthreads();
    const int Nc = nc < CMAX ? nc : CMAX;

    // 5) exact fp32 rescore: s = dot(q_row, k_cand) / 16
    for (int c = wid; c < Nc; c += 8) {
        const float* kr = g_k + (size_t)cidx[c] * D;
        float s = 0.f;
#pragma unroll
        for (int j = 0; j < 8; j++)
            s = fmaf(qs[lane + 32 * j], kr[lane + 32 * j], s);
#pragma unroll
        for (int o = 16; o; o >>= 1)
            s += __shfl_xor_sync(0xffffffff, s, o);
        if (lane == 0) rs[c] = s * (1.f / 16.f);
    }
    __syncthreads();

    // 6) exact top-16 (warp 0; lower index wins ties)
    if (wid == 0) {
        int used = 0;
        for (int t = 0; t < TOPK; t++) {
            float bv = -INFINITY; int bi = 0x7fffffff;
#pragma unroll
            for (int j = 0; j < 3; j++) {
                const int s = lane + 32 * j;
                if (s < Nc && !((used >> j) & 1)) {
                    const float v = rs[s];
                    const int  ix = cidx[s];
                    if (v > bv || (v == bv && ix < bi)) { bv = v; bi = ix; }
                }
            }
#pragma unroll
            for (int o = 16; o; o >>= 1) {
                const float ov = __shfl_xor_sync(0xffffffff, bv, o);
                const int   oi = __shfl_xor_sync(0xffffffff, bi, o);
                if (ov > bv || (ov == bv && oi < bi)) { bv = ov; bi = oi; }
            }
#pragma unroll
            for (int j = 0; j < 3; j++) {
                const int s = lane + 32 * j;
                if (s < Nc && cidx[s] == bi) used |= 1 << j;
            }
            if (lane == 0) { wsc[t] = bv; wix[t] = bi; }
        }
    }
    __syncthreads();

    // 7) softmax + v aggregation (thread owns one output dim)
    float m = wsc[0];
#pragma unroll
    for (int i = 1; i < TOPK; i++) m = fmaxf(m, wsc[i]);
    float e[TOPK]; float sum = 0.f;
#pragma unroll
    for (int i = 0; i < TOPK; i++) { e[i] = expf(wsc[i] - m); sum += e[i]; }
    const float inv = 1.f / sum;

    float accv = 0.f;
#pragma unroll
    for (int i = 0; i < TOPK; i++)
        accv = fmaf(e[i] * inv, g_v[(size_t)wix[i] * D + tid], accv);

    out[(size_t)row * D + tid] = accv;
}

// ---------------------------------------------------------------------------
extern "C" void kernel_launch(void* const* d_in, const int* in_sizes, int n_in,
                              void* d_out, int out_size)
{
    const float* ego  = (const float*)d_in[0];
    const float* side = (const float*)d_in[1];
    const float* rel  = (const float*)d_in[2];
    const float* Wq   = (const float*)d_in[3];
    const float* bq   = (const float*)d_in[4];
    const float* Wk   = (const float*)d_in[5];
    const float* bk   = (const float*)d_in[6];
    const float* Wv   = (const float*)d_in[7];
    const float* bv   = (const float*)d_in[8];
    float* out = (float*)d_out;

    dim3 blk(256);
    proj_kernel<<<dim3(2, 64), blk>>>(ego,  nullptr, Wq, bq, 0);
    proj_kernel<<<dim3(2, 64), blk>>>(side, rel,     Wk, bk, 1);
    proj_kernel<<<dim3(2, 64), blk>>>(side, nullptr, Wv, bv, 2);
    approx_kernel<<<dim3(64, 64), blk>>>();
    topk_kernel<<<NE, blk>>>(out);
}

// round 10
// speedup vs baseline: 1.5323x; 1.1610x over previous
#include <cuda_runtime.h>
#include <cuda_bf16.h>
#include <math.h>
#include <stdint.h>

// Problem constants
#define D      256
#define NE     8192
#define NS     8192
#define TOPK   16
#define CAND   48     // approx top-C candidate target
#define CMAX   96     // candidate buffer cap

// Device scratch (no allocations allowed in kernel_launch)
__device__ float g_q[NE * D];
__device__ float g_k[NS * D];
__device__ float g_v[NS * D];
__device__ __align__(16) __nv_bfloat16 g_qh[NE * D];
__device__ __align__(16) __nv_bfloat16 g_kh[NS * D];
__device__ __align__(16) __nv_bfloat16 g_sb[(size_t)NE * NS];  // 128 MB approx scores

__device__ __forceinline__ uint32_t smem_u32(const void* p) {
    uint32_t a;
    asm("{ .reg .u64 t; cvta.to.shared.u64 t, %1; cvt.u32.u64 %0, t; }"
        : "=r"(a) : "l"(p));
    return a;
}

#define LDSM_X4(r0, r1, r2, r3, addr) \
    asm volatile("ldmatrix.sync.aligned.m8n8.x4.shared.b16 {%0,%1,%2,%3}, [%4];" \
                 : "=r"(r0), "=r"(r1), "=r"(r2), "=r"(r3) : "r"(addr))

#define MMA_BF16(c, a0, a1, a2, a3, b0, b1) \
    asm volatile("mma.sync.aligned.m16n8k16.row.col.f32.bf16.bf16.f32 " \
                 "{%0,%1,%2,%3}, {%4,%5,%6,%7}, {%8,%9}, {%0,%1,%2,%3};" \
                 : "+f"((c)[0]), "+f"((c)[1]), "+f"((c)[2]), "+f"((c)[3]) \
                 : "r"(a0), "r"(a1), "r"(a2), "r"(a3), "r"(b0), "r"(b1))

#define CP_ASYNC16(saddr, gptr) \
    asm volatile("cp.async.cg.shared.global [%0], [%1], 16;" \
                 :: "r"(saddr), "l"(gptr) : "memory")
#define CP_COMMIT() asm volatile("cp.async.commit_group;" ::: "memory")
#define CP_WAIT0()  asm volatile("cp.async.wait_group 0;" ::: "memory")

// ===========================================================================
// Projection GEMM (FFMA), one launch per projection (at FFMA roofline):
//   dsel 0: q = ego@Wq^T+bq        -> fp32 g_q + bf16 g_qh
//   dsel 1: k = (side.*rel)@Wk^T+bk-> fp32 g_k + bf16 g_kh
//   dsel 2: v = side@Wv^T+bv       -> fp32 g_v
// ===========================================================================
__global__ void __launch_bounds__(256, 2)
proj_kernel(const float* __restrict__ A, const float* __restrict__ A2,
            const float* __restrict__ W, const float* __restrict__ bias,
            int dsel)
{
    const int bm = blockIdx.y;
    const int bn = blockIdx.x;

    __shared__ float As[2][16][128];
    __shared__ float Bs[2][16][128];

    const int tid = threadIdx.x;
    const int tx = tid & 15;
    const int ty = tid >> 4;

    const float* Ab  = A  + (size_t)(bm * 128) * D;
    const float* A2b = A2 ? (A2 + (size_t)(bm * 128) * D) : nullptr;
    const float* Bb  = W  + (size_t)(bn * 128) * D;

    float acc[8][8];
#pragma unroll
    for (int i = 0; i < 8; i++)
#pragma unroll
        for (int j = 0; j < 8; j++) acc[i][j] = 0.f;

    auto load_stage = [&](int buf, int k0) {
#pragma unroll
        for (int r = 0; r < 2; r++) {
            const int f   = tid + r * 256;
            const int row = f >> 2;
            const int kc  = (f & 3) * 4;
            float4 a = *(const float4*)(Ab + (size_t)row * D + k0 + kc);
            if (A2b) {
                float4 a2 = *(const float4*)(A2b + (size_t)row * D + k0 + kc);
                a.x *= a2.x; a.y *= a2.y; a.z *= a2.z; a.w *= a2.w;
            }
            As[buf][kc + 0][row] = a.x;
            As[buf][kc + 1][row] = a.y;
            As[buf][kc + 2][row] = a.z;
            As[buf][kc + 3][row] = a.w;
            float4 b = *(const float4*)(Bb + (size_t)row * D + k0 + kc);
            Bs[buf][kc + 0][row] = b.x;
            Bs[buf][kc + 1][row] = b.y;
            Bs[buf][kc + 2][row] = b.z;
            Bs[buf][kc + 3][row] = b.w;
        }
    };

    load_stage(0, 0);
    __syncthreads();

    const int nk = D / 16;
    for (int kt = 0; kt < nk; kt++) {
        const int buf = kt & 1;
        if (kt + 1 < nk) load_stage(buf ^ 1, (kt + 1) * 16);
#pragma unroll
        for (int kk = 0; kk < 16; kk++) {
            float4 a0 = *(const float4*)&As[buf][kk][ty * 8];
            float4 a1 = *(const float4*)&As[buf][kk][ty * 8 + 4];
            float4 b0 = *(const float4*)&Bs[buf][kk][tx * 8];
            float4 b1 = *(const float4*)&Bs[buf][kk][tx * 8 + 4];
            float av[8] = {a0.x, a0.y, a0.z, a0.w, a1.x, a1.y, a1.z, a1.w};
            float bvv[8] = {b0.x, b0.y, b0.z, b0.w, b1.x, b1.y, b1.z, b1.w};
#pragma unroll
            for (int i = 0; i < 8; i++)
#pragma unroll
                for (int j = 0; j < 8; j++)
                    acc[i][j] = fmaf(av[i], bvv[j], acc[i][j]);
        }
        __syncthreads();
    }

    const int col0 = bn * 128 + tx * 8;
    float bia[8];
#pragma unroll
    for (int j = 0; j < 8; j++) bia[j] = bias[col0 + j];

    float* Gf = (dsel == 0) ? g_q : (dsel == 1) ? g_k : g_v;
    __nv_bfloat16* Gh = (dsel == 0) ? g_qh : g_kh;

#pragma unroll
    for (int i = 0; i < 8; i++) {
        const int row = bm * 128 + ty * 8 + i;
        float v[8];
#pragma unroll
        for (int j = 0; j < 8; j++) v[j] = acc[i][j] + bia[j];
        float* crow = Gf + (size_t)row * D + col0;
        *(float4*)(crow)     = make_float4(v[0], v[1], v[2], v[3]);
        *(float4*)(crow + 4) = make_float4(v[4], v[5], v[6], v[7]);
        if (dsel != 2) {
            __nv_bfloat16* hrow = Gh + (size_t)row * D + col0;
#pragma unroll
            for (int j = 0; j < 4; j++)
                *(__nv_bfloat162*)(hrow + j * 2) =
                    __float22bfloat162_rn(make_float2(v[2 * j], v[2 * j + 1]));
        }
    }
}

// ===========================================================================
// Approx scores GEMM (bf16 HMMA mma.sync + cp.async) — unchanged from R9.
// ===========================================================================
__global__ void __launch_bounds__(256, 2)
approx_kernel()
{
    __shared__ __align__(16) char sm[40960];  // A0,B0,A1,B1 @ 10240 each
    const int tid  = threadIdx.x;
    const int lane = tid & 31;
    const int wid  = tid >> 5;
    const int wm   = wid >> 1;
    const int wn   = wid & 1;
    const int bm   = blockIdx.y;
    const int bn   = blockIdx.x;

    const uint32_t sb0 = smem_u32(sm);
    const uint32_t uA[2] = {sb0,         sb0 + 20480};
    const uint32_t uB[2] = {sb0 + 10240, sb0 + 30720};

    float acc[2][8][4];
#pragma unroll
    for (int mt = 0; mt < 2; mt++)
#pragma unroll
        for (int nt = 0; nt < 8; nt++)
#pragma unroll
            for (int r = 0; r < 4; r++) acc[mt][nt][r] = 0.f;

    auto load_chunk = [&](int c, int b) {
        const char* srcA = (const char*)g_qh + (size_t)(bm * 128) * 512 + c * 64;
        const char* srcB = (const char*)g_kh + (size_t)(bn * 128) * 512 + c * 64;
#pragma unroll
        for (int t = 0; t < 4; t++) {
            const int i   = tid + t * 256;
            const int til = i >> 9;
            const int idx = i & 511;
            const int r   = idx >> 2;
            const int j   = idx & 3;
            const char* s = (til ? srcB : srcA) + (size_t)r * 512 + j * 16;
            const uint32_t d = sb0 + b * 20480 + til * 10240 + r * 80 + j * 16;
            CP_ASYNC16(d, s);
        }
        CP_COMMIT();
    };

    const int g  = lane >> 3;
    const int lr = lane & 7;

    load_chunk(0, 0);
    CP_WAIT0();
    __syncthreads();

    for (int c = 0; c < 8; c++) {
        const int b = c & 1;
        if (c + 1 < 8) load_chunk(c + 1, b ^ 1);
#pragma unroll
        for (int ks = 0; ks < 2; ks++) {
            const int kb = ks * 32;
            uint32_t af[2][4], bf[8][2];
#pragma unroll
            for (int mt = 0; mt < 2; mt++) {
                const uint32_t addr = uA[b] +
                    (wm * 32 + mt * 16 + (g & 1) * 8 + lr) * 80 +
                    kb + (g >> 1) * 16;
                LDSM_X4(af[mt][0], af[mt][1], af[mt][2], af[mt][3], addr);
            }
#pragma unroll
            for (int np = 0; np < 4; np++) {
                const uint32_t addr = uB[b] +
                    (wn * 64 + np * 16 + (g >> 1) * 8 + lr) * 80 +
                    kb + (g & 1) * 16;
                uint32_t r0, r1, r2, r3;
                LDSM_X4(r0, r1, r2, r3, addr);
                bf[np * 2 + 0][0] = r0; bf[np * 2 + 0][1] = r1;
                bf[np * 2 + 1][0] = r2; bf[np * 2 + 1][1] = r3;
            }
#pragma unroll
            for (int mt = 0; mt < 2; mt++)
#pragma unroll
                for (int nt = 0; nt < 8; nt++)
                    MMA_BF16(acc[mt][nt], af[mt][0], af[mt][1], af[mt][2],
                             af[mt][3], bf[nt][0], bf[nt][1]);
        }
        CP_WAIT0();
        __syncthreads();
    }

    const int gm0 = bm * 128 + wm * 32;
    const int gn0 = bn * 128 + wn * 64;
#pragma unroll
    for (int mt = 0; mt < 2; mt++)
#pragma unroll
        for (int nt = 0; nt < 8; nt++) {
            const int r0 = gm0 + mt * 16 + (lane >> 2);
            const int c0 = gn0 + nt * 8 + (lane & 3) * 2;
            float* a = acc[mt][nt];
            *(__nv_bfloat162*)&g_sb[(size_t)r0 * NS + c0] =
                __float22bfloat162_rn(make_float2(a[0], a[1]));
            *(__nv_bfloat162*)&g_sb[(size_t)(r0 + 8) * NS + c0] =
                __float22bfloat162_rn(make_float2(a[2], a[3]));
        }
}

// ===========================================================================
// Top-K: register-resident keys + per-warp histogram atomics; single-warp
// suffix scans (2 bars each instead of 16); rank-by-counting exact top-16
// (replaces 16 serial argmax rounds). Approx top-48 -> exact fp32 rescore ->
// exact top-16 (lower index wins ties) -> softmax -> aggregate v.
// ===========================================================================
__device__ __forceinline__ unsigned k16(unsigned h) {
    return ((h & 0x8000u) ? ~h : (h | 0x8000u)) & 0xFFFFu;
}

__global__ void __launch_bounds__(256)
topk_kernel(float* __restrict__ out)
{
    const int row  = blockIdx.x;
    const int tid  = threadIdx.x;
    const int lane = tid & 31;
    const int wid  = tid >> 5;

    __shared__ int   whist[8][256];   // 8 KB per-warp histograms
    __shared__ int   hsum[256];
    __shared__ float qs[D];
    __shared__ int   cidx[CMAX];
    __shared__ float rs[CMAX];
    __shared__ float wsc[TOPK];
    __shared__ int   wix[TOPK];
    __shared__ int   sh_b1, sh_want, sh_T, nc;

    // 1) load 32 bf16 scores per thread -> monotonic u16 keys in registers
    unsigned short lk[32];
    const uint4* sp = (const uint4*)(g_sb + (size_t)row * NS);
#pragma unroll
    for (int i = 0; i < 4; i++) {
        uint4 u = sp[tid + i * 256];
        unsigned w[4] = {u.x, u.y, u.z, u.w};
#pragma unroll
        for (int j = 0; j < 4; j++) {
            lk[i * 8 + j * 2 + 0] = (unsigned short)k16(w[j] & 0xFFFFu);
            lk[i * 8 + j * 2 + 1] = (unsigned short)k16(w[j] >> 16);
        }
    }
#pragma unroll
    for (int w = 0; w < 8; w++) whist[w][tid] = 0;
    qs[tid] = g_q[(size_t)row * D + tid];
    if (tid == 0) nc = 0;
    __syncthreads();

    // 2) pass 1 histogram (high byte) into per-warp hists
#pragma unroll
    for (int i = 0; i < 32; i++)
        atomicAdd(&whist[wid][lk[i] >> 8], 1);
    __syncthreads();
    {
        int h = 0;
#pragma unroll
        for (int w = 0; w < 8; w++) h += whist[w][tid];
        hsum[tid] = h;
    }
    __syncthreads();

    // 3) warp 0: suffix scan over 256 bins (8/lane), find threshold bucket.
    //    warp 1 zeroes whist[0] for pass 2 meanwhile.
    if (wid == 0) {
        int h[8], ls[8];
        const int b0 = lane * 8;
#pragma unroll
        for (int j = 0; j < 8; j++) h[j] = hsum[b0 + j];
        int tot = 0;
#pragma unroll
        for (int j = 7; j >= 0; j--) { tot += h[j]; ls[j] = tot; }
        int acc = tot;
#pragma unroll
        for (int off = 1; off < 32; off <<= 1) {
            const int v = __shfl_down_sync(0xffffffff, acc, off);
            if (lane + off < 32) acc += v;
        }
        const int excl = acc - tot;   // sum over lanes > lane
#pragma unroll
        for (int j = 0; j < 8; j++) {
            const int S  = excl + ls[j];
            const int Sn = (j < 7) ? (excl + ls[j + 1]) : excl;
            if (S >= CAND && Sn < CAND) { sh_b1 = b0 + j; sh_want = CAND - Sn; }
        }
    } else if (wid == 1) {
#pragma unroll
        for (int j = 0; j < 8; j++) whist[0][lane * 8 + j] = 0;
    }
    __syncthreads();
    const int b1   = sh_b1;
    const int want = sh_want;

    // 4) pass 2 histogram (low byte within bucket b1)
#pragma unroll
    for (int i = 0; i < 32; i++) {
        const unsigned u = lk[i];
        if ((int)(u >> 8) == b1) atomicAdd(&whist[0][u & 255], 1);
    }
    __syncthreads();
    if (wid == 0) {
        int h[8], ls[8];
        const int b0 = lane * 8;
#pragma unroll
        for (int j = 0; j < 8; j++) h[j] = whist[0][b0 + j];
        int tot = 0;
#pragma unroll
        for (int j = 7; j >= 0; j--) { tot += h[j]; ls[j] = tot; }
        int acc = tot;
#pragma unroll
        for (int off = 1; off < 32; off <<= 1) {
            const int v = __shfl_down_sync(0xffffffff, acc, off);
            if (lane + off < 32) acc += v;
        }
        const int excl = acc - tot;
#pragma unroll
        for (int j = 0; j < 8; j++) {
            const int S  = excl + ls[j];
            const int Sn = (j < 7) ? (excl + ls[j + 1]) : excl;
            if (S >= want && Sn < want) sh_T = (b1 << 8) | (b0 + j);
        }
    }
    __syncthreads();
    const unsigned T = (unsigned)sh_T;

    // 5) collect candidate indices (key >= T)
#pragma unroll
    for (int i = 0; i < 4; i++)
#pragma unroll
        for (int jj = 0; jj < 8; jj++) {
            if (lk[i * 8 + jj] >= T) {
                const int p = atomicAdd(&nc, 1);
                if (p < CMAX) cidx[p] = (tid + i * 256) * 8 + jj;
            }
        }
    __syncthreads();
    const int Nc = nc < CMAX ? nc : CMAX;

    // 6) exact fp32 rescore: s = dot(q_row, k_cand) / 16
    for (int c = wid; c < Nc; c += 8) {
        const float* kr = g_k + (size_t)cidx[c] * D;
        float s = 0.f;
#pragma unroll
        for (int j = 0; j < 8; j++)
            s = fmaf(qs[lane + 32 * j], kr[lane + 32 * j], s);
#pragma unroll
        for (int o = 16; o; o >>= 1)
            s += __shfl_xor_sync(0xffffffff, s, o);
        if (lane == 0) rs[c] = s * (1.f / 16.f);
    }
    __syncthreads();

    // 7) exact top-16 by rank-counting: candidate t's rank = number of
    //    candidates strictly preferred under (value desc, index asc).
    if (tid < Nc) {
        const float v = rs[tid];
        const int  ix = cidx[tid];
        int rank = 0;
        for (int j = 0; j < Nc; j++) {
            const float vj = rs[j];
            const int  ij = cidx[j];
            rank += (vj > v || (vj == v && ij < ix)) ? 1 : 0;
        }
        if (rank < TOPK) { wsc[rank] = v; wix[rank] = ix; }
    }
    __syncthreads();

    // 8) softmax + v aggregation (thread owns one output dim)
    float m = wsc[0];
#pragma unroll
    for (int i = 1; i < TOPK; i++) m = fmaxf(m, wsc[i]);
    float e[TOPK]; float sum = 0.f;
#pragma unroll
    for (int i = 0; i < TOPK; i++) { e[i] = expf(wsc[i] - m); sum += e[i]; }
    const float inv = 1.f / sum;

    float accv = 0.f;
#pragma unroll
    for (int i = 0; i < TOPK; i++)
        accv = fmaf(e[i] * inv, g_v[(size_t)wix[i] * D + tid], accv);

    out[(size_t)row * D + tid] = accv;
}

// ---------------------------------------------------------------------------
extern "C" void kernel_launch(void* const* d_in, const int* in_sizes, int n_in,
                              void* d_out, int out_size)
{
    const float* ego  = (const float*)d_in[0];
    const float* side = (const float*)d_in[1];
    const float* rel  = (const float*)d_in[2];
    const float* Wq   = (const float*)d_in[3];
    const float* bq   = (const float*)d_in[4];
    const float* Wk   = (const float*)d_in[5];
    const float* bk   = (const float*)d_in[6];
    const float* Wv   = (const float*)d_in[7];
    const float* bv   = (const float*)d_in[8];
    float* out = (float*)d_out;

    dim3 blk(256);
    proj_kernel<<<dim3(2, 64), blk>>>(ego,  nullptr, Wq, bq, 0);
    proj_kernel<<<dim3(2, 64), blk>>>(side, rel,     Wk, bk, 1);
    proj_kernel<<<dim3(2, 64), blk>>>(side, nullptr, Wv, bv, 2);
    approx_kernel<<<dim3(64, 64), blk>>>();
    topk_kernel<<<NE, blk>>>(out);
}

// round 14
// speedup vs baseline: 1.5637x; 1.0205x over previous
#include <cuda_runtime.h>
#include <cuda_bf16.h>
#include <math.h>
#include <stdint.h>

// Problem constants
#define D      256
#define NE     8192
#define NS     8192
#define TOPK   16
#define CAND   48     // approx top-C candidate target
#define CMAX   96     // candidate buffer cap

// Device scratch (no allocations allowed in kernel_launch)
__device__ float g_q[NE * D];
__device__ float g_k[NS * D];
__device__ float g_v[NS * D];
__device__ __align__(16) __nv_bfloat16 g_qh[NE * D];
__device__ __align__(16) __nv_bfloat16 g_kh[NS * D];
__device__ __align__(16) __nv_bfloat16 g_sb[(size_t)NE * NS];  // 128 MB approx scores

__device__ __forceinline__ uint32_t smem_u32(const void* p) {
    uint32_t a;
    asm("{ .reg .u64 t; cvta.to.shared.u64 t, %1; cvt.u32.u64 %0, t; }"
        : "=r"(a) : "l"(p));
    return a;
}

#define LDSM_X4(r0, r1, r2, r3, addr) \
    asm volatile("ldmatrix.sync.aligned.m8n8.x4.shared.b16 {%0,%1,%2,%3}, [%4];" \
                 : "=r"(r0), "=r"(r1), "=r"(r2), "=r"(r3) : "r"(addr))

#define MMA_BF16(c, a0, a1, a2, a3, b0, b1) \
    asm volatile("mma.sync.aligned.m16n8k16.row.col.f32.bf16.bf16.f32 " \
                 "{%0,%1,%2,%3}, {%4,%5,%6,%7}, {%8,%9}, {%0,%1,%2,%3};" \
                 : "+f"((c)[0]), "+f"((c)[1]), "+f"((c)[2]), "+f"((c)[3]) \
                 : "r"(a0), "r"(a1), "r"(a2), "r"(a3), "r"(b0), "r"(b1))

#define CP_ASYNC16(saddr, gptr) \
    asm volatile("cp.async.cg.shared.global [%0], [%1], 16;" \
                 :: "r"(saddr), "l"(gptr) : "memory")
#define CP_COMMIT() asm volatile("cp.async.commit_group;" ::: "memory")
#define CP_WAIT0()  asm volatile("cp.async.wait_group 0;" ::: "memory")
#define CP_WAIT1()  asm volatile("cp.async.wait_group 1;" ::: "memory")

// ===========================================================================
// Projection GEMM (FFMA), one launch per projection (at FFMA roofline):
//   dsel 0: q = ego@Wq^T+bq        -> fp32 g_q + bf16 g_qh
//   dsel 1: k = (side.*rel)@Wk^T+bk-> fp32 g_k + bf16 g_kh
//   dsel 2: v = side@Wv^T+bv       -> fp32 g_v
// ===========================================================================
__global__ void __launch_bounds__(256, 2)
proj_kernel(const float* __restrict__ A, const float* __restrict__ A2,
            const float* __restrict__ W, const float* __restrict__ bias,
            int dsel)
{
    const int bm = blockIdx.y;
    const int bn = blockIdx.x;

    __shared__ float As[2][16][128];
    __shared__ float Bs[2][16][128];

    const int tid = threadIdx.x;
    const int tx = tid & 15;
    const int ty = tid >> 4;

    const float* Ab  = A  + (size_t)(bm * 128) * D;
    const float* A2b = A2 ? (A2 + (size_t)(bm * 128) * D) : nullptr;
    const float* Bb  = W  + (size_t)(bn * 128) * D;

    float acc[8][8];
#pragma unroll
    for (int i = 0; i < 8; i++)
#pragma unroll
        for (int j = 0; j < 8; j++) acc[i][j] = 0.f;

    auto load_stage = [&](int buf, int k0) {
#pragma unroll
        for (int r = 0; r < 2; r++) {
            const int f   = tid + r * 256;
            const int row = f >> 2;
            const int kc  = (f & 3) * 4;
            float4 a = *(const float4*)(Ab + (size_t)row * D + k0 + kc);
            if (A2b) {
                float4 a2 = *(const float4*)(A2b + (size_t)row * D + k0 + kc);
                a.x *= a2.x; a.y *= a2.y; a.z *= a2.z; a.w *= a2.w;
            }
            As[buf][kc + 0][row] = a.x;
            As[buf][kc + 1][row] = a.y;
            As[buf][kc + 2][row] = a.z;
            As[buf][kc + 3][row] = a.w;
            float4 b = *(const float4*)(Bb + (size_t)row * D + k0 + kc);
            Bs[buf][kc + 0][row] = b.x;
            Bs[buf][kc + 1][row] = b.y;
            Bs[buf][kc + 2][row] = b.z;
            Bs[buf][kc + 3][row] = b.w;
        }
    };

    load_stage(0, 0);
    __syncthreads();

    const int nk = D / 16;
    for (int kt = 0; kt < nk; kt++) {
        const int buf = kt & 1;
        if (kt + 1 < nk) load_stage(buf ^ 1, (kt + 1) * 16);
#pragma unroll
        for (int kk = 0; kk < 16; kk++) {
            float4 a0 = *(const float4*)&As[buf][kk][ty * 8];
            float4 a1 = *(const float4*)&As[buf][kk][ty * 8 + 4];
            float4 b0 = *(const float4*)&Bs[buf][kk][tx * 8];
            float4 b1 = *(const float4*)&Bs[buf][kk][tx * 8 + 4];
            float av[8] = {a0.x, a0.y, a0.z, a0.w, a1.x, a1.y, a1.z, a1.w};
            float bvv[8] = {b0.x, b0.y, b0.z, b0.w, b1.x, b1.y, b1.z, b1.w};
#pragma unroll
            for (int i = 0; i < 8; i++)
#pragma unroll
                for (int j = 0; j < 8; j++)
                    acc[i][j] = fmaf(av[i], bvv[j], acc[i][j]);
        }
        __syncthreads();
    }

    const int col0 = bn * 128 + tx * 8;
    float bia[8];
#pragma unroll
    for (int j = 0; j < 8; j++) bia[j] = bias[col0 + j];

    float* Gf = (dsel == 0) ? g_q : (dsel == 1) ? g_k : g_v;
    __nv_bfloat16* Gh = (dsel == 0) ? g_qh : g_kh;

#pragma unroll
    for (int i = 0; i < 8; i++) {
        const int row = bm * 128 + ty * 8 + i;
        float v[8];
#pragma unroll
        for (int j = 0; j < 8; j++) v[j] = acc[i][j] + bia[j];
        float* crow = Gf + (size_t)row * D + col0;
        *(float4*)(crow)     = make_float4(v[0], v[1], v[2], v[3]);
        *(float4*)(crow + 4) = make_float4(v[4], v[5], v[6], v[7]);
        if (dsel != 2) {
            __nv_bfloat16* hrow = Gh + (size_t)row * D + col0;
#pragma unroll
            for (int j = 0; j < 4; j++)
                *(__nv_bfloat162*)(hrow + j * 2) =
                    __float22bfloat162_rn(make_float2(v[2 * j], v[2 * j + 1]));
        }
    }
}

// ===========================================================================
// Approx scores GEMM (bf16 HMMA mma.sync), 3-stage cp.async ring (dynamic
// smem, 3 x 20 KB). Steady state: compute chunk c while chunk c+1 finishes
// and chunk c+2 streams.
// ===========================================================================
#define AP_STAGE  20480
#define AP_SMEM   (3 * AP_STAGE)   // 61440

__global__ void __launch_bounds__(256, 2)
approx_kernel()
{
    extern __shared__ __align__(16) char smd[];
    const int tid  = threadIdx.x;
    const int lane = tid & 31;
    const int wid  = tid >> 5;
    const int wm   = wid >> 1;
    const int wn   = wid & 1;
    const int bm   = blockIdx.y;
    const int bn   = blockIdx.x;

    const uint32_t sb0 = smem_u32(smd);

    float acc[2][8][4];
#pragma unroll
    for (int mt = 0; mt < 2; mt++)
#pragma unroll
        for (int nt = 0; nt < 8; nt++)
#pragma unroll
            for (int r = 0; r < 4; r++) acc[mt][nt][r] = 0.f;

    auto load_chunk = [&](int c, int s) {
        const char* srcA = (const char*)g_qh + (size_t)(bm * 128) * 512 + c * 64;
        const char* srcB = (const char*)g_kh + (size_t)(bn * 128) * 512 + c * 64;
#pragma unroll
        for (int t = 0; t < 4; t++) {
            const int i   = tid + t * 256;
            const int til = i >> 9;
            const int idx = i & 511;
            const int r   = idx >> 2;
            const int j   = idx & 3;
            const char* sp = (til ? srcB : srcA) + (size_t)r * 512 + j * 16;
            const uint32_t d = sb0 + s * AP_STAGE + til * 10240 + r * 80 + j * 16;
            CP_ASYNC16(d, sp);
        }
        CP_COMMIT();
    };

    const int g  = lane >> 3;
    const int lr = lane & 7;

    load_chunk(0, 0);
    load_chunk(1, 1);

    for (int c = 0; c < 8; c++) {
        if (c < 7) CP_WAIT1(); else CP_WAIT0();
        __syncthreads();                     // chunk c visible; buf (c+2)%3 free
        if (c + 2 < 8) load_chunk(c + 2, (c + 2) % 3);

        const uint32_t uAc = sb0 + (c % 3) * AP_STAGE;
        const uint32_t uBc = uAc + 10240;
#pragma unroll
        for (int ks = 0; ks < 2; ks++) {
            const int kb = ks * 32;
            uint32_t af[2][4], bf[8][2];
#pragma unroll
            for (int mt = 0; mt < 2; mt++) {
                const uint32_t addr = uAc +
                    (wm * 32 + mt * 16 + (g & 1) * 8 + lr) * 80 +
                    kb + (g >> 1) * 16;
                LDSM_X4(af[mt][0], af[mt][1], af[mt][2], af[mt][3], addr);
            }
#pragma unroll
            for (int np = 0; np < 4; np++) {
                const uint32_t addr = uBc +
                    (wn * 64 + np * 16 + (g >> 1) * 8 + lr) * 80 +
                    kb + (g & 1) * 16;
                uint32_t r0, r1, r2, r3;
                LDSM_X4(r0, r1, r2, r3, addr);
                bf[np * 2 + 0][0] = r0; bf[np * 2 + 0][1] = r1;
                bf[np * 2 + 1][0] = r2; bf[np * 2 + 1][1] = r3;
            }
#pragma unroll
            for (int mt = 0; mt < 2; mt++)
#pragma unroll
                for (int nt = 0; nt < 8; nt++)
                    MMA_BF16(acc[mt][nt], af[mt][0], af[mt][1], af[mt][2],
                             af[mt][3], bf[nt][0], bf[nt][1]);
        }
    }

    const int gm0 = bm * 128 + wm * 32;
    const int gn0 = bn * 128 + wn * 64;
#pragma unroll
    for (int mt = 0; mt < 2; mt++)
#pragma unroll
        for (int nt = 0; nt < 8; nt++) {
            const int r0 = gm0 + mt * 16 + (lane >> 2);
            const int c0 = gn0 + nt * 8 + (lane & 3) * 2;
            float* a = acc[mt][nt];
            *(__nv_bfloat162*)&g_sb[(size_t)r0 * NS + c0] =
                __float22bfloat162_rn(make_float2(a[0], a[1]));
            *(__nv_bfloat162*)&g_sb[(size_t)(r0 + 8) * NS + c0] =
                __float22bfloat162_rn(make_float2(a[2], a[3]));
        }
}

// ===========================================================================
// Top-K: packed register keys (2 per u32), launch_bounds (256,4), per-warp
// histogram atomics, single-warp suffix scans, half-warp-per-candidate exact
// fp32 rescore with PADDED trip count (all half-warps run identical
// iterations so full-warp shuffles stay convergent — the unpadded loop
// deadlocked in R11), rank-counting exact top-16, softmax, aggregate v.
// ===========================================================================
__device__ __forceinline__ unsigned k16(unsigned h) {
    return ((h & 0x8000u) ? ~h : (h | 0x8000u)) & 0xFFFFu;
}

__global__ void __launch_bounds__(256, 4)
topk_kernel(float* __restrict__ out)
{
    const int row  = blockIdx.x;
    const int tid  = threadIdx.x;
    const int lane = tid & 31;
    const int wid  = tid >> 5;

    __shared__ int   whist[8][256];   // 8 KB per-warp histograms
    __shared__ int   hsum[256];
    __shared__ float qs[D];
    __shared__ int   cidx[CMAX];
    __shared__ float rs[CMAX];
    __shared__ float wsc[TOPK];
    __shared__ int   wix[TOPK];
    __shared__ int   sh_b1, sh_want, sh_T, nc;

    // 1) load 32 bf16 scores per thread -> 16 packed u32 (2 u16 keys each)
    unsigned pk[16];
    const uint4* sp = (const uint4*)(g_sb + (size_t)row * NS);
#pragma unroll
    for (int i = 0; i < 4; i++) {
        uint4 u = sp[tid + i * 256];
        unsigned w[4] = {u.x, u.y, u.z, u.w};
#pragma unroll
        for (int j = 0; j < 4; j++)
            pk[i * 4 + j] = k16(w[j] & 0xFFFFu) | (k16(w[j] >> 16) << 16);
    }
#pragma unroll
    for (int w = 0; w < 8; w++) whist[w][tid] = 0;
    qs[tid] = g_q[(size_t)row * D + tid];
    if (tid == 0) nc = 0;
    __syncthreads();

    // 2) pass 1 histogram (high byte of each key) into per-warp hists
#pragma unroll
    for (int p = 0; p < 16; p++) {
        atomicAdd(&whist[wid][(pk[p] >> 8) & 0xFFu], 1);
        atomicAdd(&whist[wid][pk[p] >> 24], 1);
    }
    __syncthreads();
    {
        int h = 0;
#pragma unroll
        for (int w = 0; w < 8; w++) h += whist[w][tid];
        hsum[tid] = h;
    }
    __syncthreads();

    // 3) warp 0: suffix scan over 256 bins, find threshold bucket;
    //    warp 1 zeroes whist[0] for pass 2 meanwhile.
    if (wid == 0) {
        int h[8], ls[8];
        const int b0 = lane * 8;
#pragma unroll
        for (int j = 0; j < 8; j++) h[j] = hsum[b0 + j];
        int tot = 0;
#pragma unroll
        for (int j = 7; j >= 0; j--) { tot += h[j]; ls[j] = tot; }
        int acc = tot;
#pragma unroll
        for (int off = 1; off < 32; off <<= 1) {
            const int v = __shfl_down_sync(0xffffffff, acc, off);
            if (lane + off < 32) acc += v;
        }
        const int excl = acc - tot;   // sum over lanes > lane
#pragma unroll
        for (int j = 0; j < 8; j++) {
            const int S  = excl + ls[j];
            const int Sn = (j < 7) ? (excl + ls[j + 1]) : excl;
            if (S >= CAND && Sn < CAND) { sh_b1 = b0 + j; sh_want = CAND - Sn; }
        }
    } else if (wid == 1) {
#pragma unroll
        for (int j = 0; j < 8; j++) whist[0][lane * 8 + j] = 0;
    }
    __syncthreads();
    const int b1   = sh_b1;
    const int want = sh_want;

    // 4) pass 2 histogram (low byte within bucket b1)
#pragma unroll
    for (int p = 0; p < 16; p++) {
        const unsigned v = pk[p];
        if ((int)((v >> 8) & 0xFFu) == b1) atomicAdd(&whist[0][v & 0xFFu], 1);
        if ((int)(v >> 24) == b1)          atomicAdd(&whist[0][(v >> 16) & 0xFFu], 1);
    }
    __syncthreads();
    if (wid == 0) {
        int h[8], ls[8];
        const int b0 = lane * 8;
#pragma unroll
        for (int j = 0; j < 8; j++) h[j] = whist[0][b0 + j];
        int tot = 0;
#pragma unroll
        for (int j = 7; j >= 0; j--) { tot += h[j]; ls[j] = tot; }
        int acc = tot;
#pragma unroll
        for (int off = 1; off < 32; off <<= 1) {
            const int v = __shfl_down_sync(0xffffffff, acc, off);
            if (lane + off < 32) acc += v;
        }
        const int excl = acc - tot;
#pragma unroll
        for (int j = 0; j < 8; j++) {
            const int S  = excl + ls[j];
            const int Sn = (j < 7) ? (excl + ls[j + 1]) : excl;
            if (S >= want && Sn < want) sh_T = (b1 << 8) | (b0 + j);
        }
    }
    __syncthreads();
    const unsigned T = (unsigned)sh_T;

    // 5) collect candidate indices (key >= T)
#pragma unroll
    for (int p = 0; p < 16; p++) {
        const unsigned v = pk[p];
        const int base = (tid + (p >> 2) * 256) * 8 + (p & 3) * 2;
        if ((v & 0xFFFFu) >= T) {
            const int q2 = atomicAdd(&nc, 1);
            if (q2 < CMAX) cidx[q2] = base;
        }
        if ((v >> 16) >= T) {
            const int q2 = atomicAdd(&nc, 1);
            if (q2 < CMAX) cidx[q2] = base + 1;
        }
    }
    __syncthreads();
    const int Nc = nc < CMAX ? nc : CMAX;

    // 6) exact fp32 rescore, half-warp per candidate, PADDED trip count so
    //    full-warp shuffles remain convergent across both half-warps.
    {
        const int hw  = tid >> 4;
        const int hl  = tid & 15;
        const int NcR = (Nc + 15) & ~15;          // multiple of 16
        for (int c = hw; c < NcR; c += 16) {
            const bool live = (c < Nc);
            const float* kr = g_k + (size_t)(live ? cidx[c] : 0) * D;
            float s = 0.f;
#pragma unroll
            for (int j = 0; j < 16; j++)
                s = fmaf(qs[hl + 16 * j], kr[hl + 16 * j], s);
#pragma unroll
            for (int o = 8; o; o >>= 1)
                s += __shfl_xor_sync(0xffffffff, s, o);
            if (live && hl == 0) rs[c] = s * (1.f / 16.f);
        }
    }
    __syncthreads();

    // 7) exact top-16 by rank-counting (value desc, index asc)
    if (tid < Nc) {
        const float v = rs[tid];
        const int  ix = cidx[tid];
        int rank = 0;
        for (int j = 0; j < Nc; j++) {
            const float vj = rs[j];
            const int  ij = cidx[j];
            rank += (vj > v || (vj == v && ij < ix)) ? 1 : 0;
        }
        if (rank < TOPK) { wsc[rank] = v; wix[rank] = ix; }
    }
    __syncthreads();

    // 8) softmax + v aggregation (thread owns one output dim)
    float m = wsc[0];
#pragma unroll
    for (int i = 1; i < TOPK; i++) m = fmaxf(m, wsc[i]);
    float e[TOPK]; float sum = 0.f;
#pragma unroll
    for (int i = 0; i < TOPK; i++) { e[i] = expf(wsc[i] - m); sum += e[i]; }
    const float inv = 1.f / sum;

    float accv = 0.f;
#pragma unroll
    for (int i = 0; i < TOPK; i++)
        accv = fmaf(e[i] * inv, g_v[(size_t)wix[i] * D + tid], accv);

    out[(size_t)row * D + tid] = accv;
}

// ---------------------------------------------------------------------------
extern "C" void kernel_launch(void* const* d_in, const int* in_sizes, int n_in,
                              void* d_out, int out_size)
{
    const float* ego  = (const float*)d_in[0];
    const float* side = (const float*)d_in[1];
    const float* rel  = (const float*)d_in[2];
    const float* Wq   = (const float*)d_in[3];
    const float* bq   = (const float*)d_in[4];
    const float* Wk   = (const float*)d_in[5];
    const float* bk   = (const float*)d_in[6];
    const float* Wv   = (const float*)d_in[7];
    const float* bv   = (const float*)d_in[8];
    float* out = (float*)d_out;

    cudaFuncSetAttribute(approx_kernel,
                         cudaFuncAttributeMaxDynamicSharedMemorySize, AP_SMEM);

    dim3 blk(256);
    proj_kernel<<<dim3(2, 64), blk>>>(ego,  nullptr, Wq, bq, 0);
    proj_kernel<<<dim3(2, 64), blk>>>(side, rel,     Wk, bk, 1);
    proj_kernel<<<dim3(2, 64), blk>>>(side, nullptr, Wv, bv, 2);
    approx_kernel<<<dim3(64, 64), blk, AP_SMEM>>>();
    topk_kernel<<<NE, blk>>>(out);
}